// round 1
// baseline (speedup 1.0000x reference)
#include <cuda_runtime.h>
#include <math.h>
#include <stdint.h>

// RVQE: 12-qubit real statevector recurrent cell, B=64, T=9 (8 scan steps).
// One CTA per batch element; state = 4096 floats = 128 threads x 32 registers.
// Global amplitude index g (12 bits): bit (11-l) <-> lane l.
//   local bits 0..4 (within thread): lanes 11(anc1),10(anc0),9,8,7
//   thread bits 0..4 (warp lane):    lanes 6,5,4,3,2   -> __shfl_xor
//   thread bits 5,6  (warp id):      lanes 1,0         -> smem exchange

namespace {

constexpr int NTH   = 128;
constexpr int TT    = 9;
constexpr int NSTEP = 8;

__device__ __forceinline__ void ry_pair(float& a, float& b, float c, float s) {
    float a0 = a, b0 = b;
    a = fmaf(-s, b0, c * a0);   // p0' = c p0 - s p1
    b = fmaf( s, a0, c * b0);   // p1' = s p0 + c p1
}

template <int K>
__device__ __forceinline__ void ry_local(float* v, float c, float s) {
#pragma unroll
    for (int r = 0; r < 32; r++)
        if (!(r & (1 << K))) ry_pair(v[r], v[r | (1 << K)], c, s);
}

__device__ __forceinline__ void ry_shfl(float* v, int t, int m, float c, float s) {
    float se = (t & m) ? s : -s;
#pragma unroll
    for (int r = 0; r < 32; r++) {
        float w = __shfl_xor_sync(0xffffffffu, v[r], m);
        v[r] = fmaf(se, w, c * v[r]);
    }
}

// Combined RY(lane0) * RY(lane1): one smem round-trip, 4-way gather.
__device__ __forceinline__ void ry_smem2(float* v, int t,
                                         float c0, float s0, float c1, float s1,
                                         float* exch) {
#pragma unroll
    for (int r = 0; r < 32; r++) exch[t * 33 + r] = v[r];
    __syncthreads();
    int a  = (t >> 6) & 1;   // lane0 bit
    int bb = (t >> 5) & 1;   // lane1 bit
    // R[0][0]=c, R[0][1]=-s, R[1][0]=s, R[1][1]=c
    float r0a0 = a  ? s0 : c0;
    float r0a1 = a  ? c0 : -s0;
    float r1b0 = bb ? s1 : c1;
    float r1b1 = bb ? c1 : -s1;
    float k00 = r0a0 * r1b0, k01 = r0a0 * r1b1;
    float k10 = r0a1 * r1b0, k11 = r0a1 * r1b1;
    int base = t & 31;
    const float* x00 = exch + base * 33;
    const float* x01 = exch + (base | 32) * 33;
    const float* x10 = exch + (base | 64) * 33;
    const float* x11 = exch + (base | 96) * 33;
#pragma unroll
    for (int r = 0; r < 32; r++) {
        v[r] = fmaf(k00, x00[r],
               fmaf(k01, x01[r],
               fmaf(k10, x10[r], k11 * x11[r])));
    }
    __syncthreads();
}

// CiY(target = local bit K, sign=+1, ctrl anc1 (local bit0 == 1))
template <int K>
__device__ __forceinline__ void ciy_local(float* v) {
#pragma unroll
    for (int r = 0; r < 32; r++)
        if ((r & 1) && !(r & (1 << K))) {
            float p0 = v[r];
            v[r] = v[r | (1 << K)];   // p0' = +p1
            v[r | (1 << K)] = -p0;    // p1' = -p0
        }
}

__device__ __forceinline__ void ciy_shfl(float* v, int t, int m) {
    float se = (t & m) ? -1.f : 1.f;
#pragma unroll
    for (int i = 0; i < 16; i++) {
        int r = 2 * i + 1;
        float w = __shfl_xor_sync(0xffffffffu, v[r], m);
        v[r] = se * w;
    }
}

__device__ __forceinline__ void ciy_smem(float* v, int t, int m, float* exch) {
#pragma unroll
    for (int i = 0; i < 16; i++) exch[t * 33 + i] = v[2 * i + 1];
    __syncthreads();
    int p = t ^ m;
    float se = (t & m) ? -1.f : 1.f;
#pragma unroll
    for (int i = 0; i < 16; i++) v[2 * i + 1] = se * exch[p * 33 + i];
    __syncthreads();
}

// Fused level-1 block: U(+1) -> CiY(anc1, sig, ctrl anc0) -> U(-1),
// one 4x4 per group of (anc0, anc1), angle-per-group via cg/sg.
// v index r = (g<<2) | (anc0<<1) | anc1.
__device__ __forceinline__ void applyL(float* v, const float* cg, const float* sg, float sig) {
#pragma unroll
    for (int g = 0; g < 8; g++) {
        float c = cg[g], s = sg[g];
        float p00 = v[4 * g + 0], p01 = v[4 * g + 1];
        float p10 = v[4 * g + 2], p11 = v[4 * g + 3];
        float q00 = fmaf(-s, p10, c * p00);
        float q10 = fmaf( s, p00, c * p10);
        float q01 = fmaf(-s, p11, c * p01);
        float q11 = fmaf( s, p01, c * p11);
        float r10 =  sig * q11;
        float r11 = -sig * q10;
        v[4 * g + 0] = fmaf( s, r10, c * q00);
        v[4 * g + 2] = fmaf(-s, q00, c * r10);
        v[4 * g + 1] = fmaf( s, r11, c * q01);
        v[4 * g + 3] = fmaf(-s, q01, c * r11);
    }
}

__global__ void __launch_bounds__(NTH, 1) rvqe_kernel(
    const int*   __restrict__ inputs,   // (64, 9, 6) int32
    const float* __restrict__ ua,       // (2, 10)
    const float* __restrict__ nth,      // (2, 10, 11)
    float*       __restrict__ out,
    int out_size)
{
    __shared__ float exch[NTH * 33];         // cross-warp exchange (padded)
    __shared__ float uc[20], us[20];         // stage RY cos/sin(theta/2)
    __shared__ float dcs[20][8], dss[20][8]; // delta tables over lanes 7..9
    __shared__ float cbs[20][NTH], sbs[20][NTH]; // per-thread base angle trig
    __shared__ float probs_sm[64];
    __shared__ int   tIdx[TT];

    const int t = threadIdx.x;
    const int b = blockIdx.x;
    const int* inb = inputs + b * TT * 6;

    // ---- precompute ----
    if (t < 20) {
        float c, s; sincosf(0.5f * ua[t], &s, &c);
        uc[t] = c; us[t] = s;
    }
    for (int idx = t; idx < 160; idx += NTH) {
        int sn = idx >> 3, g = idx & 7;
        const float* th = nth + sn * 11;
        float d = 0.f;
        if (g & 1) d += th[9];   // local bit2 = lane9
        if (g & 2) d += th[8];   // local bit3 = lane8
        if (g & 4) d += th[7];   // local bit4 = lane7
        float c, s; sincosf(0.5f * d, &s, &c);
        dcs[sn][g] = c; dss[sn][g] = s;
    }
    for (int sn = 0; sn < 20; sn++) {
        const float* th = nth + sn * 11;
        float base = th[10];
#pragma unroll
        for (int i = 0; i < 7; i++)            // lane i -> thread bit (6-i)
            if ((t >> (6 - i)) & 1) base += th[i];
        float c, s; sincosf(0.5f * base, &s, &c);
        cbs[sn][t] = c; sbs[sn][t] = s;
    }
    if (t < TT) {
        int idx = 0;
#pragma unroll
        for (int i = 0; i < 6; i++) idx |= (inb[t * 6 + i] & 1) << (5 - i);
        tIdx[t] = idx;
    }
    __syncthreads();

    // ---- init state: |inpt_0, 0...0> lands at thread (tIdx[0]<<1), reg 0 ----
    float v[32];
#pragma unroll
    for (int r = 0; r < 32; r++) v[r] = 0.f;
    if (t == (tIdx[0] << 1)) v[0] = 1.f;

    for (int step = 0; step < NSTEP; step++) {
        for (int s = 0; s < 2; s++) {
            const float* ucc = uc + s * 10;
            const float* uss = us + s * 10;
            // stage RYs (all commute; order free)
            ry_local<2>(v, ucc[9], uss[9]);
            ry_local<3>(v, ucc[8], uss[8]);
            ry_local<4>(v, ucc[7], uss[7]);
            for (int l = 2; l <= 6; l++)
                ry_shfl(v, t, 1 << (6 - l), ucc[l], uss[l]);
            ry_smem2(v, t, ucc[0], uss[0], ucc[1], uss[1], exch);

            // neurons, in order (they share ancillas: must be sequential)
            for (int n = 0; n < 10; n++) {
                int sn = s * 10 + n;
                float cb = cbs[sn][t], sb = sbs[sn][t];
                float cg[8], sg[8];
#pragma unroll
                for (int g = 0; g < 8; g++) {
                    float dc_ = dcs[sn][g], ds_ = dss[sn][g];
                    cg[g] = fmaf(cb, dc_, -sb * ds_);
                    sg[g] = fmaf(sb, dc_,  cb * ds_);
                }
                applyL(v, cg, sg, 1.f);
                if (n >= 7) {
                    if (n == 7)      ciy_local<4>(v);  // lane7 -> bit4
                    else if (n == 8) ciy_local<3>(v);  // lane8 -> bit3
                    else             ciy_local<2>(v);  // lane9 -> bit2
                } else if (n >= 2) {
                    ciy_shfl(v, t, 1 << (6 - n));
                } else {
                    ciy_smem(v, t, (n == 0) ? 64 : 32, exch);
                }
                applyL(v, cg, sg, -1.f);
            }
        }

        // ---- probs over lanes 0..5 (= thread bits 6..1): pair-sum ----
        float ssq = 0.f;
#pragma unroll
        for (int r = 0; r < 32; r++) ssq = fmaf(v[r], v[r], ssq);
        float tot = ssq + __shfl_xor_sync(0xffffffffu, ssq, 1);
        if (!(t & 1)) {
            probs_sm[t >> 1] = tot;
            out[(b * NSTEP + step) * 64 + (t >> 1)] = tot;
        }
        __syncthreads();

        // ---- project onto trgt, normalize; end-of-step and next-step
        //      cond_flips cancel exactly (trgt_k == inpt_{k+1}) ----
        int tj = tIdx[step + 1];
        float invn = 1.0f / sqrtf(probs_sm[tj]);
        if ((t >> 1) == tj) {
#pragma unroll
            for (int r = 0; r < 32; r++) v[r] *= invn;
        } else {
#pragma unroll
            for (int r = 0; r < 32; r++) v[r] = 0.f;
        }
        // (next write to probs_sm / exch is behind later __syncthreads)
    }

    // ---- second tuple output: measured = inputs[:,1:] as float ----
    if (out_size > 32768 && t < 48) {
        out[32768 + b * 48 + t] = (float)inb[6 + t];
    }
}

} // namespace

extern "C" void kernel_launch(void* const* d_in, const int* in_sizes, int n_in,
                              void* d_out, int out_size) {
    const int*   inputs = nullptr;
    const float* ua     = nullptr;
    const float* nth    = nullptr;
    // identify by element count: inputs=64*9*6=3456, ua=20, nth=220
    for (int i = 0; i < n_in; i++) {
        if (in_sizes[i] == 3456)      inputs = (const int*)d_in[i];
        else if (in_sizes[i] == 20)   ua     = (const float*)d_in[i];
        else if (in_sizes[i] == 220)  nth    = (const float*)d_in[i];
    }
    rvqe_kernel<<<64, NTH>>>(inputs, ua, nth, (float*)d_out, out_size);
}